// round 1
// baseline (speedup 1.0000x reference)
#include <cuda_runtime.h>

namespace {
constexpr int Bb = 4, Nn = 16, Tt = 2048, Ff = 512, NC = 43;
constexpr int BT = Bb * Tt;  // 8192
}

// ---------------- scratch (device globals; no allocation allowed) ------------
__device__ float g_table2[NC * Ff];                 // W1a @ emb_table^T  [43,512]
__device__ float g_Wc[Ff * 4];                      // W1b @ W_lin        [512,4]
__device__ float g_Wm2[Ff * Nn * Ff];               // Wm transposed      [f][n][c]
__device__ float g_Y[(long long)BT * Nn * Ff];      // em @ relu(em @ pre)  256MB
__device__ float g_node2[(long long)BT * Nn * Ff];  // relu(Y @ W2^T)       256MB
__device__ float g_feat[(long long)BT * Ff];        // pre-LN features      16MB

// ---------------- packed fp32x2 helpers (Blackwell FFMA2: 2x fp32 tput) ------
__device__ __forceinline__ void ffma2(unsigned long long &c,
                                      unsigned long long a,
                                      unsigned long long b) {
    asm("fma.rn.f32x2 %0, %1, %2, %0;" : "+l"(c) : "l"(a), "l"(b));
}
__device__ __forceinline__ unsigned long long pdup(float x) {
    unsigned long long r;
    asm("mov.b64 %0, {%1, %1};" : "=l"(r) : "f"(x));
    return r;
}
__device__ __forceinline__ float2 unpk(unsigned long long v) {
    float2 r;
    asm("mov.b64 {%0, %1}, %2;" : "=f"(r.x), "=f"(r.y) : "l"(v));
    return r;
}

// ---------------- precompute: table2 = W1a@emb^T, Wc = W1b@W_lin -------------
__global__ void kprep(const float* __restrict__ W1, const float* __restrict__ emb,
                      const float* __restrict__ Wlin) {
    __shared__ float se[Ff];
    __shared__ float sw[Ff * 4];
    int f = threadIdx.x;   // 512 threads
    int c = blockIdx.x;
    if (c < NC) {
        se[f] = emb[c * Ff + f];
        __syncthreads();
        float s = 0.f;
        const float* w = W1 + (size_t)f * (2 * Ff);
        #pragma unroll 8
        for (int k = 0; k < Ff; k++) s = fmaf(w[k], se[k], s);
        g_table2[c * Ff + f] = s;
    } else {
        #pragma unroll
        for (int q = 0; q < 4; q++) sw[f + q * Ff] = Wlin[f + q * Ff];
        __syncthreads();
        float s0 = 0.f, s1 = 0.f, s2 = 0.f, s3 = 0.f;
        const float* w = W1 + (size_t)f * (2 * Ff) + Ff;
        #pragma unroll 4
        for (int k = 0; k < Ff; k++) {
            float v = w[k];
            s0 = fmaf(v, sw[k * 4 + 0], s0);
            s1 = fmaf(v, sw[k * 4 + 1], s1);
            s2 = fmaf(v, sw[k * 4 + 2], s2);
            s3 = fmaf(v, sw[k * 4 + 3], s3);
        }
        g_Wc[f * 4 + 0] = s0; g_Wc[f * 4 + 1] = s1;
        g_Wc[f * 4 + 2] = s2; g_Wc[f * 4 + 3] = s3;
    }
}

// ---------------- precompute: Wm2[f][n][c] = Wm[f][c][n] ---------------------
__global__ void ktrans(const float* __restrict__ Wm) {
    int idx = blockIdx.x * 1024 + threadIdx.x;   // total Ff*Nn*Ff
    int c = idx & (Ff - 1);
    int n = (idx >> 9) & (Nn - 1);
    int f = idx >> 13;
    g_Wm2[idx] = Wm[((size_t)f * Ff + c) * Nn + n];
}

// ---------------- stage 1: build pre via lookups, Y = em @ relu(em @ pre) ----
__global__ void k1(const float* __restrict__ bbox, const int* __restrict__ cls,
                   const float* __restrict__ edge) {
    int bt = blockIdx.x;
    int b = bt >> 11, t = bt & (Tt - 1);
    __shared__ float em[Nn][Nn];
    __shared__ int   scls[Nn];
    __shared__ float sbb[Nn][4];
    int tid = threadIdx.x;   // 256
    {
        int i = tid >> 4, j = tid & 15;
        em[i][j] = edge[((size_t)(b * Nn + i) * Nn + j) * Tt + t];
    }
    if (tid < Nn) scls[tid] = cls[(size_t)(b * Nn + tid) * Tt + t];
    if (tid < Nn * 4) {
        int j = tid >> 2, c = tid & 3;
        sbb[j][c] = bbox[((size_t)(b * Nn + j) * 4 + c) * Tt + t];
    }
    __syncthreads();
    #pragma unroll
    for (int fi = 0; fi < 2; fi++) {
        int f = tid + fi * 256;
        float4 wc = *(const float4*)&g_Wc[f * 4];
        float p[Nn];
        #pragma unroll
        for (int j = 0; j < Nn; j++) {
            p[j] = g_table2[scls[j] * Ff + f]
                 + wc.x * sbb[j][0] + wc.y * sbb[j][1]
                 + wc.z * sbb[j][2] + wc.w * sbb[j][3];
        }
        float n1[Nn];
        #pragma unroll
        for (int i = 0; i < Nn; i++) {
            float s = 0.f;
            #pragma unroll
            for (int j = 0; j < Nn; j++) s = fmaf(em[i][j], p[j], s);
            n1[i] = fmaxf(s, 0.f);
        }
        #pragma unroll
        for (int i = 0; i < Nn; i++) {
            float s = 0.f;
            #pragma unroll
            for (int j = 0; j < Nn; j++) s = fmaf(em[i][j], n1[j], s);
            g_Y[((size_t)bt * Nn + i) * Ff + f] = s;
        }
    }
}

// ---------------- SGEMM (NT): C[M,512] = op(A[M,K] @ Bm[512,K]^T) ------------
// STAGE 0: A=g_Y,    Bm=W2 (param), C=g_node2, relu epilogue
// STAGE 1: A=g_node2,Bm=g_Wm2,      C=g_feat,  no relu
template<int STAGE>
__global__ void __launch_bounds__(256, 2)
sgemm(const float* __restrict__ W2p, int M, int K) {
    const float* __restrict__ A  = (STAGE == 0) ? (const float*)g_Y : (const float*)g_node2;
    const float* __restrict__ Bm = (STAGE == 0) ? W2p : (const float*)g_Wm2;
    float* __restrict__ C        = (STAGE == 0) ? (float*)g_node2 : (float*)g_feat;

    constexpr int BM = 128, BN = 128, BK = 16;
    __shared__ __align__(16) float As[BK][BM];
    __shared__ __align__(16) float Bs[BK][BN];

    int tid = threadIdx.x;
    int m0 = blockIdx.x * BM;
    int n0 = blockIdx.y * BN;
    int tr = tid >> 4;        // 0..15 -> 8 rows each
    int tc = tid & 15;        // 0..15 -> 8 cols each
    int lrow = tid >> 2;      // 0..63
    int lk   = (tid & 3) * 4; // 0,4,8,12

    unsigned long long acc[8][4];
    #pragma unroll
    for (int i = 0; i < 8; i++)
        #pragma unroll
        for (int j = 0; j < 4; j++) acc[i][j] = 0ULL;

    for (int k0 = 0; k0 < K; k0 += BK) {
        #pragma unroll
        for (int l = 0; l < 2; l++) {
            int r = lrow + l * 64;
            float4 va = *(const float4*)&A[(size_t)(m0 + r) * K + k0 + lk];
            As[lk + 0][r] = va.x; As[lk + 1][r] = va.y;
            As[lk + 2][r] = va.z; As[lk + 3][r] = va.w;
            float4 vb = *(const float4*)&Bm[(size_t)(n0 + r) * K + k0 + lk];
            Bs[lk + 0][r] = vb.x; Bs[lk + 1][r] = vb.y;
            Bs[lk + 2][r] = vb.z; Bs[lk + 3][r] = vb.w;
        }
        __syncthreads();
        #pragma unroll
        for (int kk = 0; kk < BK; kk++) {
            float4 a0 = *(const float4*)&As[kk][tr * 8];
            float4 a1 = *(const float4*)&As[kk][tr * 8 + 4];
            ulonglong2 b0 = *(const ulonglong2*)&Bs[kk][tc * 8];
            ulonglong2 b1 = *(const ulonglong2*)&Bs[kk][tc * 8 + 4];
            unsigned long long ap[8];
            ap[0] = pdup(a0.x); ap[1] = pdup(a0.y); ap[2] = pdup(a0.z); ap[3] = pdup(a0.w);
            ap[4] = pdup(a1.x); ap[5] = pdup(a1.y); ap[6] = pdup(a1.z); ap[7] = pdup(a1.w);
            #pragma unroll
            for (int i = 0; i < 8; i++) {
                ffma2(acc[i][0], ap[i], b0.x);
                ffma2(acc[i][1], ap[i], b0.y);
                ffma2(acc[i][2], ap[i], b1.x);
                ffma2(acc[i][3], ap[i], b1.y);
            }
        }
        __syncthreads();
    }

    #pragma unroll
    for (int i = 0; i < 8; i++) {
        size_t row = (size_t)(m0 + tr * 8 + i) * Ff + n0 + tc * 8;
        float2 p0 = unpk(acc[i][0]), p1 = unpk(acc[i][1]);
        float2 p2 = unpk(acc[i][2]), p3 = unpk(acc[i][3]);
        float4 o0 = make_float4(p0.x, p0.y, p1.x, p1.y);
        float4 o1 = make_float4(p2.x, p2.y, p3.x, p3.y);
        if (STAGE == 0) {
            o0.x = fmaxf(o0.x, 0.f); o0.y = fmaxf(o0.y, 0.f);
            o0.z = fmaxf(o0.z, 0.f); o0.w = fmaxf(o0.w, 0.f);
            o1.x = fmaxf(o1.x, 0.f); o1.y = fmaxf(o1.y, 0.f);
            o1.z = fmaxf(o1.z, 0.f); o1.w = fmaxf(o1.w, 0.f);
        }
        *(float4*)&C[row]     = o0;
        *(float4*)&C[row + 4] = o1;
    }
}

// ---------------- LayerNorm over F + transpose to [B,F,T] --------------------
__global__ void kln(const float* __restrict__ lnw, const float* __restrict__ lnb,
                    float* __restrict__ out) {
    int bt = blockIdx.x;
    int b = bt >> 11, t = bt & (Tt - 1);
    int tid = threadIdx.x;   // 256
    float v0 = g_feat[(size_t)bt * Ff + tid];
    float v1 = g_feat[(size_t)bt * Ff + 256 + tid];
    __shared__ float red[16];
    float s = v0 + v1;
    #pragma unroll
    for (int o = 16; o > 0; o >>= 1) s += __shfl_xor_sync(0xffffffffu, s, o);
    if ((tid & 31) == 0) red[tid >> 5] = s;
    __syncthreads();
    float mu = (red[0] + red[1] + red[2] + red[3] +
                red[4] + red[5] + red[6] + red[7]) * (1.f / Ff);
    float r0 = v0 - mu, r1 = v1 - mu;
    float q = r0 * r0 + r1 * r1;
    #pragma unroll
    for (int o = 16; o > 0; o >>= 1) q += __shfl_xor_sync(0xffffffffu, q, o);
    if ((tid & 31) == 0) red[8 + (tid >> 5)] = q;
    __syncthreads();
    float var = (red[8] + red[9] + red[10] + red[11] +
                 red[12] + red[13] + red[14] + red[15]) * (1.f / Ff);
    float inv = rsqrtf(var + 1e-5f);
    out[((size_t)b * Ff + tid) * Tt + t]       = r0 * inv * lnw[tid] + lnb[tid];
    out[((size_t)b * Ff + tid + 256) * Tt + t] = r1 * inv * lnw[tid + 256] + lnb[tid + 256];
}

// ---------------- launch ------------------------------------------------------
extern "C" void kernel_launch(void* const* d_in, const int* in_sizes, int n_in,
                              void* d_out, int out_size) {
    const float* bbox = (const float*)d_in[0];
    const int*   cls  = (const int*)d_in[1];
    const float* edge = (const float*)d_in[2];
    const float* Wlin = (const float*)d_in[3];
    const float* emb  = (const float*)d_in[4];
    const float* W1   = (const float*)d_in[5];
    const float* W2   = (const float*)d_in[6];
    const float* Wm   = (const float*)d_in[7];
    const float* lnw  = (const float*)d_in[8];
    const float* lnb  = (const float*)d_in[9];
    float* out = (float*)d_out;

    kprep<<<NC + 1, Ff>>>(W1, emb, Wlin);
    ktrans<<<(Ff * Nn * Ff) / 1024, 1024>>>(Wm);
    k1<<<BT, 256>>>(bbox, cls, edge);
    sgemm<0><<<dim3((BT * Nn) / 128, Ff / 128), 256>>>(W2, BT * Nn, Ff);
    sgemm<1><<<dim3(BT / 128, Ff / 128), 256>>>(nullptr, BT, Nn * Ff);
    kln<<<BT, 256>>>(lnw, lnb, out);
}

// round 3
// speedup vs baseline: 2.7636x; 2.7636x over previous
#include <cuda_runtime.h>
#include <cstdint>

namespace {
constexpr int Bb = 4, Nn = 16, Tt = 2048, Ff = 512, NC = 43;
constexpr int BT = Bb * Tt;  // 8192
}

// ---------------- scratch (device globals; no allocation allowed) ------------
__device__ float g_table2[NC * Ff];
__device__ float g_Wc[Ff * 4];
__device__ float g_W2r[Ff * Ff];                    // tf32-rounded W2
__device__ float g_Wm2[Ff * Nn * Ff];               // tf32-rounded Wm^T [f][n][c]
__device__ float g_Y[(long long)BT * Nn * Ff];      // 256MB (tf32-rounded)
__device__ float g_node2[(long long)BT * Nn * Ff];  // 256MB (tf32-rounded)
__device__ float g_feat[(long long)BT * Ff];        // 16MB (full fp32)

// ---------------- helpers -----------------------------------------------------
__device__ __forceinline__ uint32_t smem_u32(const void* p) {
    uint32_t a;
    asm("{ .reg .u64 t; cvta.to.shared.u64 t, %1; cvt.u32.u64 %0, t; }" : "=r"(a) : "l"(p));
    return a;
}
__device__ __forceinline__ void cpa16(uint32_t s, const void* g) {
    asm volatile("cp.async.cg.shared.global [%0], [%1], 16;" :: "r"(s), "l"(g) : "memory");
}
__device__ __forceinline__ float tf32r(float x) {
    uint32_t r;
    asm("cvt.rna.tf32.f32 %0, %1;" : "=r"(r) : "f"(x));
    return __uint_as_float(r);
}
__device__ __forceinline__ void mma_tf32(float* c, const uint32_t* a, const uint32_t* b) {
    asm volatile(
        "mma.sync.aligned.m16n8k8.row.col.f32.tf32.tf32.f32 "
        "{%0,%1,%2,%3}, {%4,%5,%6,%7}, {%8,%9}, {%0,%1,%2,%3};"
        : "+f"(c[0]), "+f"(c[1]), "+f"(c[2]), "+f"(c[3])
        : "r"(a[0]), "r"(a[1]), "r"(a[2]), "r"(a[3]), "r"(b[0]), "r"(b[1]));
}

// ---------------- precompute: table2 = W1a@emb^T, Wc = W1b@W_lin -------------
__global__ void kprep(const float* __restrict__ W1, const float* __restrict__ emb,
                      const float* __restrict__ Wlin) {
    __shared__ float se[Ff];
    __shared__ float sw[Ff * 4];
    int f = threadIdx.x;
    int c = blockIdx.x;
    if (c < NC) {
        se[f] = emb[c * Ff + f];
        __syncthreads();
        float s = 0.f;
        const float* w = W1 + (size_t)f * (2 * Ff);
        #pragma unroll 8
        for (int k = 0; k < Ff; k++) s = fmaf(w[k], se[k], s);
        g_table2[c * Ff + f] = s;
    } else {
        #pragma unroll
        for (int q = 0; q < 4; q++) sw[f + q * Ff] = Wlin[f + q * Ff];
        __syncthreads();
        float s0 = 0.f, s1 = 0.f, s2 = 0.f, s3 = 0.f;
        const float* w = W1 + (size_t)f * (2 * Ff) + Ff;
        #pragma unroll 4
        for (int k = 0; k < Ff; k++) {
            float v = w[k];
            s0 = fmaf(v, sw[k * 4 + 0], s0);
            s1 = fmaf(v, sw[k * 4 + 1], s1);
            s2 = fmaf(v, sw[k * 4 + 2], s2);
            s3 = fmaf(v, sw[k * 4 + 3], s3);
        }
        g_Wc[f * 4 + 0] = s0; g_Wc[f * 4 + 1] = s1;
        g_Wc[f * 4 + 2] = s2; g_Wc[f * 4 + 3] = s3;
    }
}

// ---------------- precompute: Wm2[f][n][c] = tf32(Wm[f][c][n]), W2r = tf32(W2)
__global__ void ktrans(const float* __restrict__ Wm) {
    int idx = blockIdx.x * 1024 + threadIdx.x;
    int c = idx & (Ff - 1);
    int n = (idx >> 9) & (Nn - 1);
    int f = idx >> 13;
    g_Wm2[idx] = tf32r(Wm[((size_t)f * Ff + c) * Nn + n]);
}
__global__ void kw2(const float* __restrict__ W2) {
    int i = blockIdx.x * 1024 + threadIdx.x;
    g_W2r[i] = tf32r(W2[i]);
}

// ---------------- stage 1: build pre via lookups, Y = em @ relu(em @ pre) ----
__global__ void k1(const float* __restrict__ bbox, const int* __restrict__ cls,
                   const float* __restrict__ edge) {
    int bt = blockIdx.x;
    int b = bt >> 11, t = bt & (Tt - 1);
    __shared__ float em[Nn][Nn];
    __shared__ int   scls[Nn];
    __shared__ float sbb[Nn][4];
    int tid = threadIdx.x;   // 256
    {
        int i = tid >> 4, j = tid & 15;
        em[i][j] = edge[((size_t)(b * Nn + i) * Nn + j) * Tt + t];
    }
    if (tid < Nn) scls[tid] = cls[(size_t)(b * Nn + tid) * Tt + t];
    if (tid < Nn * 4) {
        int j = tid >> 2, c = tid & 3;
        sbb[j][c] = bbox[((size_t)(b * Nn + j) * 4 + c) * Tt + t];
    }
    __syncthreads();
    #pragma unroll
    for (int fi = 0; fi < 2; fi++) {
        int f = tid + fi * 256;
        float4 wc = *(const float4*)&g_Wc[f * 4];
        float p[Nn];
        #pragma unroll
        for (int j = 0; j < Nn; j++) {
            p[j] = g_table2[scls[j] * Ff + f]
                 + wc.x * sbb[j][0] + wc.y * sbb[j][1]
                 + wc.z * sbb[j][2] + wc.w * sbb[j][3];
        }
        float n1[Nn];
        #pragma unroll
        for (int i = 0; i < Nn; i++) {
            float s = 0.f;
            #pragma unroll
            for (int j = 0; j < Nn; j++) s = fmaf(em[i][j], p[j], s);
            n1[i] = fmaxf(s, 0.f);
        }
        #pragma unroll
        for (int i = 0; i < Nn; i++) {
            float s = 0.f;
            #pragma unroll
            for (int j = 0; j < Nn; j++) s = fmaf(em[i][j], n1[j], s);
            g_Y[((size_t)bt * Nn + i) * Ff + f] = tf32r(s);
        }
    }
}

// ---------------- tf32 mma.sync GEMM: C[M,512] = op(A[M,K] @ Bw[512,K]^T) ----
// BM=128, BN=128, BK=32; 256 thr = 8 warps (2 M x 4 N), warp tile 64x32.
// Double-buffered cp.async. SMEM stride 36 words (pad 4) -> conflict-free frags.
// RELU_CVT=1: relu + tf32-round epilogue (GEMM1). 0: plain store (GEMM2).
template<int RELU_CVT>
__global__ void __launch_bounds__(256, 2)
mgemm(const float* __restrict__ A, const float* __restrict__ Bw,
      float* __restrict__ C, int K) {
    constexpr int LDSW = 36;                    // words per smem row
    constexpr int SW   = 2 * 128 * LDSW;        // words per stage (A+B) = 9216
    extern __shared__ float sm[];
    const uint32_t smb = smem_u32(sm);
    const uint32_t* __restrict__ smu = (const uint32_t*)sm;

    int tid = threadIdx.x;
    int wid = tid >> 5, lane = tid & 31;
    int g = lane >> 2, t4 = lane & 3;
    int wm = wid & 1, wn = wid >> 1;            // 2 x 4 warp grid
    size_t m0 = (size_t)blockIdx.x * 128;
    size_t n0 = (size_t)blockIdx.y * 128;
    const float* Ab = A + m0 * (size_t)K;
    const float* Bb = Bw + n0 * (size_t)K;

    int nk = K >> 5;
    int lrow = tid >> 3, lc = (tid & 7) * 4;    // loader: row 0..31 base, col

    float acc[4][4][4];
    #pragma unroll
    for (int i = 0; i < 4; i++)
        #pragma unroll
        for (int j = 0; j < 4; j++)
            #pragma unroll
            for (int q = 0; q < 4; q++) acc[i][j][q] = 0.f;

    // ---- stage loader: A 128x32 + B 128x32 (each thread 4+4 cp.async.16) ----
    auto load_stage = [&](int s, int kt) {
        uint32_t base = smb + (uint32_t)s * SW * 4;
        size_t kof = (size_t)kt * 32;
        #pragma unroll
        for (int i = 0; i < 4; i++) {
            int row = lrow + i * 32;
            cpa16(base + (row * LDSW + lc) * 4, Ab + (size_t)row * K + kof + lc);
        }
        uint32_t bbase = base + 128 * LDSW * 4;
        #pragma unroll
        for (int i = 0; i < 4; i++) {
            int row = lrow + i * 32;
            cpa16(bbase + (row * LDSW + lc) * 4, Bb + (size_t)row * K + kof + lc);
        }
    };

    load_stage(0, 0);
    asm volatile("cp.async.commit_group;" ::: "memory");

    for (int kt = 0; kt < nk; kt++) {
        if (kt + 1 < nk) {
            load_stage((kt + 1) & 1, kt + 1);
            asm volatile("cp.async.commit_group;" ::: "memory");
            asm volatile("cp.async.wait_group 1;" ::: "memory");
        } else {
            asm volatile("cp.async.wait_group 0;" ::: "memory");
        }
        __syncthreads();

        const uint32_t* Su = smu + (kt & 1) * SW;
        const uint32_t* Bu = Su + 128 * LDSW;
        #pragma unroll
        for (int kk = 0; kk < 32; kk += 8) {
            uint32_t a[4][4], bfr[4][2];
            int ac = kk + t4;
            #pragma unroll
            for (int mt = 0; mt < 4; mt++) {
                int r = wm * 64 + mt * 16 + g;
                a[mt][0] = Su[r * LDSW + ac];
                a[mt][1] = Su[(r + 8) * LDSW + ac];
                a[mt][2] = Su[r * LDSW + ac + 4];
                a[mt][3] = Su[(r + 8) * LDSW + ac + 4];
            }
            #pragma unroll
            for (int nt = 0; nt < 4; nt++) {
                int r = wn * 32 + nt * 8 + g;
                bfr[nt][0] = Bu[r * LDSW + ac];
                bfr[nt][1] = Bu[r * LDSW + ac + 4];
            }
            #pragma unroll
            for (int mt = 0; mt < 4; mt++)
                #pragma unroll
                for (int nt = 0; nt < 4; nt++)
                    mma_tf32(acc[mt][nt], a[mt], bfr[nt]);
        }
        __syncthreads();
    }

    // ---- epilogue ----
    #pragma unroll
    for (int mt = 0; mt < 4; mt++) {
        #pragma unroll
        for (int nt = 0; nt < 4; nt++) {
            size_t row = m0 + wm * 64 + mt * 16 + g;
            size_t col = n0 + wn * 32 + nt * 8 + t4 * 2;
            float v0 = acc[mt][nt][0], v1 = acc[mt][nt][1];
            float v2 = acc[mt][nt][2], v3 = acc[mt][nt][3];
            if (RELU_CVT) {
                v0 = tf32r(fmaxf(v0, 0.f)); v1 = tf32r(fmaxf(v1, 0.f));
                v2 = tf32r(fmaxf(v2, 0.f)); v3 = tf32r(fmaxf(v3, 0.f));
            }
            *(float2*)&C[row * 512 + col]       = make_float2(v0, v1);
            *(float2*)&C[(row + 8) * 512 + col] = make_float2(v2, v3);
        }
    }
}

// ---------------- LayerNorm over F + transpose to [B,F,T] --------------------
__global__ void kln(const float* __restrict__ lnw, const float* __restrict__ lnb,
                    float* __restrict__ out) {
    int bt = blockIdx.x;
    int b = bt >> 11, t = bt & (Tt - 1);
    int tid = threadIdx.x;   // 256
    float v0 = g_feat[(size_t)bt * Ff + tid];
    float v1 = g_feat[(size_t)bt * Ff + 256 + tid];
    __shared__ float red[16];
    float s = v0 + v1;
    #pragma unroll
    for (int o = 16; o > 0; o >>= 1) s += __shfl_xor_sync(0xffffffffu, s, o);
    if ((tid & 31) == 0) red[tid >> 5] = s;
    __syncthreads();
    float mu = (red[0] + red[1] + red[2] + red[3] +
                red[4] + red[5] + red[6] + red[7]) * (1.f / Ff);
    float r0 = v0 - mu, r1 = v1 - mu;
    float q = r0 * r0 + r1 * r1;
    #pragma unroll
    for (int o = 16; o > 0; o >>= 1) q += __shfl_xor_sync(0xffffffffu, q, o);
    if ((tid & 31) == 0) red[8 + (tid >> 5)] = q;
    __syncthreads();
    float var = (red[8] + red[9] + red[10] + red[11] +
                 red[12] + red[13] + red[14] + red[15]) * (1.f / Ff);
    float inv = rsqrtf(var + 1e-5f);
    out[((size_t)b * Ff + tid) * Tt + t]       = r0 * inv * lnw[tid] + lnb[tid];
    out[((size_t)b * Ff + tid + 256) * Tt + t] = r1 * inv * lnw[tid + 256] + lnb[tid + 256];
}

// ---------------- launch ------------------------------------------------------
extern "C" void kernel_launch(void* const* d_in, const int* in_sizes, int n_in,
                              void* d_out, int out_size) {
    const float* bbox = (const float*)d_in[0];
    const int*   cls  = (const int*)d_in[1];
    const float* edge = (const float*)d_in[2];
    const float* Wlin = (const float*)d_in[3];
    const float* emb  = (const float*)d_in[4];
    const float* W1   = (const float*)d_in[5];
    const float* W2   = (const float*)d_in[6];
    const float* Wm   = (const float*)d_in[7];
    const float* lnw  = (const float*)d_in[8];
    const float* lnb  = (const float*)d_in[9];
    float* out = (float*)d_out;

    void *pY, *pN2, *pF, *pWm2, *pW2r;
    cudaGetSymbolAddress(&pY, g_Y);
    cudaGetSymbolAddress(&pN2, g_node2);
    cudaGetSymbolAddress(&pF, g_feat);
    cudaGetSymbolAddress(&pWm2, g_Wm2);
    cudaGetSymbolAddress(&pW2r, g_W2r);

    const int SMEMSZ = 2 * 2 * 128 * 36 * 4;   // 73728 B
    cudaFuncSetAttribute(mgemm<1>, cudaFuncAttributeMaxDynamicSharedMemorySize, SMEMSZ);
    cudaFuncSetAttribute(mgemm<0>, cudaFuncAttributeMaxDynamicSharedMemorySize, SMEMSZ);

    kprep<<<NC + 1, Ff>>>(W1, emb, Wlin);
    ktrans<<<(Ff * Nn * Ff) / 1024, 1024>>>(Wm);
    kw2<<<(Ff * Ff) / 1024, 1024>>>(W2);
    k1<<<BT, 256>>>(bbox, cls, edge);
    // GEMM1: node2 = tf32(relu(Y @ W2r^T))   [131072 x 512] x [512 x 512]
    mgemm<1><<<dim3((BT * Nn) / 128, Ff / 128), 256, SMEMSZ>>>(
        (const float*)pY, (const float*)pW2r, (float*)pN2, Ff);
    // GEMM2: feat = node2 @ Wm2^T            [8192 x 8192] x [512 x 8192]
    mgemm<0><<<dim3(BT / 128, Ff / 128), 256, SMEMSZ>>>(
        (const float*)pN2, (const float*)pWm2, (float*)pF, Nn * Ff);
    kln<<<BT, 256>>>(lnw, lnb, out);
}